// round 7
// baseline (speedup 1.0000x reference)
#include <cuda_runtime.h>
#include <cstddef>

#define BATCH 16
#define NN 128
#define DD 128
#define EE 64
#define HH 256
#define ROWS (BATCH*NN)   // 2048
#define EPSLN 1e-5f

#define GRELU 1
#define GMASK 2

// ---------------- scratch (static device buffers, no allocation) ----------------
__device__ float g_x[ROWS*DD];
__device__ float g_np[ROWS*HH];
__device__ float g_s[ROWS*HH];
__device__ float g_agg[ROWS*HH];
__device__ float g_u1[ROWS*HH];
__device__ float g_u[ROWS*DD];
__device__ float g_cnt[ROWS];

// ---------------- helpers ----------------
__device__ __forceinline__ unsigned f2tf(float f) {
    unsigned r;
    asm("cvt.rna.tf32.f32 %0, %1;" : "=r"(r) : "f"(f));
    return r;
}

// hi/lo split: hi = tf32(v), lo = tf32(v - hi)   (3xTF32 scheme)
__device__ __forceinline__ void tfsplit(float v, unsigned& hi, unsigned& lo) {
    hi = f2tf(v);
    lo = f2tf(v - __uint_as_float(hi));
}

__device__ __forceinline__ void mma_tf32(float* d,
                                         unsigned a0, unsigned a1, unsigned a2, unsigned a3,
                                         unsigned b0, unsigned b1) {
    asm volatile("mma.sync.aligned.m16n8k8.row.col.f32.tf32.tf32.f32 "
                 "{%0,%1,%2,%3}, {%4,%5,%6,%7}, {%8,%9}, {%0,%1,%2,%3};"
                 : "+f"(d[0]), "+f"(d[1]), "+f"(d[2]), "+f"(d[3])
                 : "r"(a0), "r"(a1), "r"(a2), "r"(a3), "r"(b0), "r"(b1));
}

// ---------------- prep: x = nodes * mask ----------------
__global__ void prep_x_kernel(const float* __restrict__ nodes,
                              const int* __restrict__ mask,
                              float* __restrict__ x) {
    int row = blockIdx.x;         // 0..2047
    int d = threadIdx.x;          // 0..127
    float mi = mask[row] ? 1.f : 0.f;
    x[row*DD + d] = nodes[row*DD + d] * mi;
}

// cnt[b*N+i] = mask[b,i] * sum_j mask[b,j]
__global__ void prep_cnt_kernel(const int* __restrict__ mask,
                                float* __restrict__ cnt) {
    int b = blockIdx.x;
    int j = threadIdx.x;          // 0..127
    __shared__ float red[NN];
    float m = mask[b*NN + j] ? 1.f : 0.f;
    red[j] = m;
    __syncthreads();
    for (int s2 = 64; s2 > 0; s2 >>= 1) {
        if (j < s2) red[j] += red[j + s2];
        __syncthreads();
    }
    cnt[b*NN + j] = m * red[0];
}

// ---------------- tf32 tensor-core edge kernel (k-permuted smem) ----------------
// s[b,i,h] = m_i * sum_j m_j * relu( np[b,i,h] + b1[h] + sum_e E[j,e]*W[e,h] )
// Smem stores element (j, e=k*8+cc) at sE[j*68 + cc*8 + k], so each thread's
// 8-k fragment series is contiguous -> LDS.128 instead of 4x scalar LDS.
__global__ __launch_bounds__(256, 2)
void edge_msg_tc(const float* __restrict__ edges,
                 const float* __restrict__ We,    // (64,256)
                 const float* __restrict__ b1,    // (256)
                 const float* __restrict__ np,    // (ROWS,256)
                 const int* __restrict__ mask,
                 float* __restrict__ s_out) {
    __shared__ __align__(16) unsigned sE[128 * 68];  // 34816 B, tf32 bits, k-permuted
    __shared__ float smj[NN];

    int row = blockIdx.x;              // b*N + i
    int b = row >> 7;
    int t = threadIdx.x;
    int w = t >> 5;
    int lane = t & 31;
    int hb = w * 32;
    int r = lane >> 2;                 // 0..7  (row group)
    int c = lane & 3;                  // 0..3  (col group)

    // ---- stage E tile (128 j-rows x 64 e) into k-permuted smem as tf32 ----
    const float4* src = (const float4*)(edges + (size_t)row * NN * EE);
#pragma unroll
    for (int g = t; g < 2048; g += 256) {   // 2048 float4
        float4 v = src[g];
        int rr = g >> 4;
        int e0 = (g & 15) * 4;          // e0 % 8 in {0,4}: all 4 elems share k
        int k  = e0 >> 3;
        int cc0 = e0 & 7;               // 0 or 4
        unsigned* d = &sE[rr * 68 + k];
        d[(cc0 + 0) * 8] = f2tf(v.x);
        d[(cc0 + 1) * 8] = f2tf(v.y);
        d[(cc0 + 2) * 8] = f2tf(v.z);
        d[(cc0 + 3) * 8] = f2tf(v.w);
    }
    if (t < NN) smj[t] = mask[b*NN + t] ? 1.f : 0.f;

    // ---- preload B fragments: W[64,256] row-major(k,h) ----
    unsigned B0[4][8], B1[4][8];
#pragma unroll
    for (int nt = 0; nt < 4; nt++) {
        int col = hb + nt*8 + r;
#pragma unroll
        for (int k = 0; k < 8; k++) {
            B0[nt][k] = f2tf(We[(k*8 + c)     * HH + col]);
            B1[nt][k] = f2tf(We[(k*8 + c + 4) * HH + col]);
        }
    }

    // ---- npv = np + b1 for this lane's h columns ----
    float npv0[4], npv1[4];
#pragma unroll
    for (int nt = 0; nt < 4; nt++) {
        int h = hb + nt*8 + 2*c;
        npv0[nt] = np[(size_t)row*HH + h]     + b1[h];
        npv1[nt] = np[(size_t)row*HH + h + 1] + b1[h + 1];
    }

    float s0[4] = {0.f, 0.f, 0.f, 0.f};
    float s1[4] = {0.f, 0.f, 0.f, 0.f};

    __syncthreads();

    // ---- main loop: 8 m-tiles of 16 j-rows ----
#pragma unroll 1
    for (int m0 = 0; m0 < 8; m0++) {
        float acc[4][4];
#pragma unroll
        for (int nt = 0; nt < 4; nt++) {
            acc[nt][0] = 0.f; acc[nt][1] = 0.f; acc[nt][2] = 0.f; acc[nt][3] = 0.f;
        }
        int row0 = (m0*16 + r) * 68;
        int row1 = (m0*16 + r + 8) * 68;

        unsigned A0[8], A1[8], A2[8], A3[8];
        *(uint4*)&A0[0] = *(const uint4*)&sE[row0 + c*8];
        *(uint4*)&A0[4] = *(const uint4*)&sE[row0 + c*8 + 4];
        *(uint4*)&A1[0] = *(const uint4*)&sE[row1 + c*8];
        *(uint4*)&A1[4] = *(const uint4*)&sE[row1 + c*8 + 4];
        *(uint4*)&A2[0] = *(const uint4*)&sE[row0 + (c+4)*8];
        *(uint4*)&A2[4] = *(const uint4*)&sE[row0 + (c+4)*8 + 4];
        *(uint4*)&A3[0] = *(const uint4*)&sE[row1 + (c+4)*8];
        *(uint4*)&A3[4] = *(const uint4*)&sE[row1 + (c+4)*8 + 4];

#pragma unroll
        for (int k = 0; k < 8; k++) {
#pragma unroll
            for (int nt = 0; nt < 4; nt++)
                mma_tf32(acc[nt], A0[k], A1[k], A2[k], A3[k], B0[nt][k], B1[nt][k]);
        }

        float mj0 = smj[m0*16 + r];
        float mj1 = smj[m0*16 + r + 8];
#pragma unroll
        for (int nt = 0; nt < 4; nt++) {
            s0[nt] += mj0 * fmaxf(acc[nt][0] + npv0[nt], 0.f)
                    + mj1 * fmaxf(acc[nt][2] + npv0[nt], 0.f);
            s1[nt] += mj0 * fmaxf(acc[nt][1] + npv1[nt], 0.f)
                    + mj1 * fmaxf(acc[nt][3] + npv1[nt], 0.f);
        }
    }

    // ---- cross-lane reduce over row groups ----
#pragma unroll
    for (int off = 4; off < 32; off <<= 1) {
#pragma unroll
        for (int nt = 0; nt < 4; nt++) {
            s0[nt] += __shfl_xor_sync(0xffffffffu, s0[nt], off);
            s1[nt] += __shfl_xor_sync(0xffffffffu, s1[nt], off);
        }
    }

    float mi = mask[row] ? 1.f : 0.f;
    if (lane < 4) {
#pragma unroll
        for (int nt = 0; nt < 4; nt++) {
            int h = hb + nt*8 + 2*lane;
            s_out[(size_t)row*HH + h]     = mi * s0[nt];
            s_out[(size_t)row*HH + h + 1] = mi * s1[nt];
        }
    }
}

// ---------------- 3xTF32 split tensor-core GEMM, double-buffered ----------------
// C(M,N) = epilogue( [A | A2](M,K) @ W(K,N) ), near-fp32 accuracy via
// Ah*Bh + Al*Bh + Ah*Bl. Block tile 64x64, 128 threads (2x2 warps, warp 32x32),
// K-chunk 32. Requires M%64==0, N%64==0, K%32==0, K1%32==0.
__global__ __launch_bounds__(128)
void gemm_tc(int M, int N, int K, int K1,
             const float* __restrict__ A, int lda,
             const float* __restrict__ A2, int lda2,
             const float* __restrict__ W, int ldw,
             const float* __restrict__ bias,
             const float* __restrict__ rowscale,
             const int* __restrict__ maskrow,
             float* __restrict__ C, int ldc, int flags) {
    __shared__ __align__(16) float sA[2][64 * 36];   // raw fp32, stride 36
    __shared__ __align__(16) float sB[2][32 * 72];   // raw fp32, stride 72

    int tid = threadIdx.x;
    int w = tid >> 5;
    int lane = tid & 31;
    int wm = w & 1, wn = w >> 1;       // 2x2 warp grid
    int r = lane >> 2, c = lane & 3;

    int bm = blockIdx.y * 64, bn = blockIdx.x * 64;

    float acc[2][4][4];
#pragma unroll
    for (int mt = 0; mt < 2; mt++)
#pragma unroll
        for (int nt = 0; nt < 4; nt++)
#pragma unroll
            for (int i = 0; i < 4; i++) acc[mt][nt][i] = 0.f;

    float4 pa[4], pb[4];

#define PREFETCH(k0_) do {                                                   \
    _Pragma("unroll")                                                        \
    for (int q = 0; q < 4; q++) {                                            \
        int g = tid + q*128;                                                 \
        int row_ = g >> 3, col4 = (g & 7) * 4;                               \
        int gm = bm + row_, gk = (k0_) + col4;                               \
        if (A2 != nullptr && gk >= K1)                                       \
            pa[q] = *(const float4*)(A2 + (size_t)gm*lda2 + (gk - K1));      \
        else                                                                 \
            pa[q] = *(const float4*)(A + (size_t)gm*lda + gk);               \
    }                                                                        \
    _Pragma("unroll")                                                        \
    for (int q = 0; q < 4; q++) {                                            \
        int g = tid + q*128;                                                 \
        int row_ = g >> 4, col4 = (g & 15) * 4;                              \
        pb[q] = *(const float4*)(W + (size_t)((k0_) + row_)*ldw + bn + col4);\
    }                                                                        \
} while (0)

#define STORE_STAGE(s_) do {                                                 \
    _Pragma("unroll")                                                        \
    for (int q = 0; q < 4; q++) {                                            \
        int g = tid + q*128;                                                 \
        int row_ = g >> 3, col4 = (g & 7) * 4;                               \
        *(float4*)&sA[s_][row_*36 + col4] = pa[q];                           \
    }                                                                        \
    _Pragma("unroll")                                                        \
    for (int q = 0; q < 4; q++) {                                            \
        int g = tid + q*128;                                                 \
        int row_ = g >> 4, col4 = (g & 15) * 4;                              \
        *(float4*)&sB[s_][row_*72 + col4] = pb[q];                           \
    }                                                                        \
} while (0)

    PREFETCH(0);
    STORE_STAGE(0);
    __syncthreads();

    int s = 0;
    for (int k0 = 0; ; ) {
        bool haveNext = (k0 + 32 < K);
        if (haveNext) PREFETCH(k0 + 32);

        // compute on buffer s
#pragma unroll
        for (int kk = 0; kk < 4; kk++) {
            unsigned bh0[4], bl0[4], bh1[4], bl1[4];
#pragma unroll
            for (int nt = 0; nt < 4; nt++) {
                int col = wn*32 + nt*8 + r;
                tfsplit(sB[s][(kk*8 + c)     * 72 + col], bh0[nt], bl0[nt]);
                tfsplit(sB[s][(kk*8 + c + 4) * 72 + col], bh1[nt], bl1[nt]);
            }
#pragma unroll
            for (int mt = 0; mt < 2; mt++) {
                int row0 = (wm*32 + mt*16 + r) * 36;
                int row1 = (wm*32 + mt*16 + r + 8) * 36;
                unsigned ah0, al0, ah1, al1, ah2, al2, ah3, al3;
                tfsplit(sA[s][row0 + kk*8 + c],     ah0, al0);
                tfsplit(sA[s][row1 + kk*8 + c],     ah1, al1);
                tfsplit(sA[s][row0 + kk*8 + c + 4], ah2, al2);
                tfsplit(sA[s][row1 + kk*8 + c + 4], ah3, al3);
#pragma unroll
                for (int nt = 0; nt < 4; nt++) {
                    mma_tf32(acc[mt][nt], ah0, ah1, ah2, ah3, bh0[nt], bh1[nt]);
                    mma_tf32(acc[mt][nt], al0, al1, al2, al3, bh0[nt], bh1[nt]);
                    mma_tf32(acc[mt][nt], ah0, ah1, ah2, ah3, bl0[nt], bl1[nt]);
                }
            }
        }

        k0 += 32;
        if (!haveNext) break;
        STORE_STAGE(s ^ 1);       // other buffer: no race with readers of s
        __syncthreads();
        s ^= 1;
    }
#undef PREFETCH
#undef STORE_STAGE

    // epilogue
#pragma unroll
    for (int mt = 0; mt < 2; mt++) {
#pragma unroll
        for (int i2 = 0; i2 < 2; i2++) {      // row sub (r / r+8)
            int gm = bm + wm*32 + mt*16 + r + i2*8;
            float rs = (rowscale != nullptr) ? rowscale[gm] : 1.f;
            float mf = (flags & GMASK) ? (maskrow[gm] ? 1.f : 0.f) : 1.f;
#pragma unroll
            for (int nt = 0; nt < 4; nt++) {
#pragma unroll
                for (int j = 0; j < 2; j++) {
                    int gn = bn + wn*32 + nt*8 + 2*c + j;
                    float v = acc[mt][nt][i2*2 + j];
                    if (bias != nullptr) v += bias[gn] * rs;
                    if (flags & GRELU) v = fmaxf(v, 0.f);
                    v *= mf;
                    C[(size_t)gm*ldc + gn] = v;
                }
            }
        }
    }
}

// ---------------- fused residual + LayerNorm: x = LN(x + u*mi)*g + b, then *mi ----
__global__ void ln_kernel(const float* __restrict__ u,
                          const int* __restrict__ mask,
                          const float* __restrict__ gw,
                          const float* __restrict__ bw,
                          float* __restrict__ x) {
    int warp = threadIdx.x >> 5;
    int lane = threadIdx.x & 31;
    int row = blockIdx.x * 8 + warp;
    float mi = mask[row] ? 1.f : 0.f;

    float v[4];
#pragma unroll
    for (int q = 0; q < 4; q++) {
        int d = lane + q*32;
        v[q] = x[(size_t)row*DD + d] + u[(size_t)row*DD + d] * mi;
    }
    float s = v[0] + v[1] + v[2] + v[3];
#pragma unroll
    for (int o = 16; o > 0; o >>= 1) s += __shfl_xor_sync(0xffffffffu, s, o);
    float mu = s * (1.f / DD);
    float var = 0.f;
#pragma unroll
    for (int q = 0; q < 4; q++) { float d2 = v[q] - mu; var += d2*d2; }
#pragma unroll
    for (int o = 16; o > 0; o >>= 1) var += __shfl_xor_sync(0xffffffffu, var, o);
    float rstd = rsqrtf(var * (1.f / DD) + EPSLN);
#pragma unroll
    for (int q = 0; q < 4; q++) {
        int d = lane + q*32;
        x[(size_t)row*DD + d] = ((v[q] - mu) * rstd * gw[d] + bw[d]) * mi;
    }
}

// ---------------- host launch ----------------
extern "C" void kernel_launch(void* const* d_in, const int* in_sizes, int n_in,
                              void* d_out, int out_size) {
    const float* nodes  = (const float*)d_in[0];
    const float* edges  = (const float*)d_in[1];
    const int*   mask   = (const int*)d_in[2];
    const float* msg_w1 = (const float*)d_in[3];   // (L,192,256)
    const float* msg_b1 = (const float*)d_in[4];   // (L,256)
    const float* msg_w2 = (const float*)d_in[5];   // (L,256,256)
    const float* msg_b2 = (const float*)d_in[6];   // (L,256)
    const float* upd_w1 = (const float*)d_in[7];   // (L,384,256)
    const float* upd_b1 = (const float*)d_in[8];   // (L,256)
    const float* upd_w2 = (const float*)d_in[9];   // (L,256,128)
    const float* upd_b2 = (const float*)d_in[10];  // (L,128)
    const float* ln_g   = (const float*)d_in[11];  // (L,128)
    const float* ln_b   = (const float*)d_in[12];  // (L,128)
    const float* out_w1 = (const float*)d_in[13];  // (128,256)
    const float* out_b1 = (const float*)d_in[14];  // (256)
    const float* out_w2 = (const float*)d_in[15];  // (256,128)
    const float* out_b2 = (const float*)d_in[16];  // (128)
    float* out = (float*)d_out;

    float *x, *np, *s, *agg, *u1, *u, *cnt;
    cudaGetSymbolAddress((void**)&x,   g_x);
    cudaGetSymbolAddress((void**)&np,  g_np);
    cudaGetSymbolAddress((void**)&s,   g_s);
    cudaGetSymbolAddress((void**)&agg, g_agg);
    cudaGetSymbolAddress((void**)&u1,  g_u1);
    cudaGetSymbolAddress((void**)&u,   g_u);
    cudaGetSymbolAddress((void**)&cnt, g_cnt);

    prep_x_kernel<<<ROWS, DD>>>(nodes, mask, x);
    prep_cnt_kernel<<<BATCH, NN>>>(mask, cnt);

    for (int l = 0; l < 3; l++) {
        const float* w1n = msg_w1 + (size_t)l * 192 * HH;          // node part rows 0..127
        const float* w1e = w1n + (size_t)DD * HH;                  // edge part rows 128..191
        const float* b1  = msg_b1 + (size_t)l * HH;
        const float* w2  = msg_w2 + (size_t)l * HH * HH;
        const float* b2  = msg_b2 + (size_t)l * HH;
        const float* uw1 = upd_w1 + (size_t)l * 384 * HH;
        const float* ub1 = upd_b1 + (size_t)l * HH;
        const float* uw2 = upd_w2 + (size_t)l * HH * DD;
        const float* ub2 = upd_b2 + (size_t)l * DD;
        const float* lg  = ln_g + (size_t)l * DD;
        const float* lb  = ln_b + (size_t)l * DD;

        // np = x @ w1n      (2048,256,K=128)
        gemm_tc<<<dim3(HH/64, ROWS/64), 128>>>(ROWS, HH, DD, 0,
            x, DD, nullptr, 0, w1n, HH, nullptr, nullptr, nullptr, np, HH, 0);

        // s = masked relu-reduce of (np + edges@w1e + b1)   [tf32 tensor cores]
        edge_msg_tc<<<ROWS, 256>>>(edges, w1e, b1, np, mask, s);

        // agg = s @ w2 + cnt*b2   (2048,256,K=256)
        gemm_tc<<<dim3(HH/64, ROWS/64), 128>>>(ROWS, HH, HH, 0,
            s, HH, nullptr, 0, w2, HH, b2, cnt, nullptr, agg, HH, 0);

        // u1 = relu([x,agg] @ uw1 + ub1)   (2048,256,K=384, split at 128)
        gemm_tc<<<dim3(HH/64, ROWS/64), 128>>>(ROWS, HH, DD + HH, DD,
            x, DD, agg, HH, uw1, HH, ub1, nullptr, nullptr, u1, HH, GRELU);

        // u = u1 @ uw2 + ub2   (2048,128,K=256)
        gemm_tc<<<dim3(DD/64, ROWS/64), 128>>>(ROWS, DD, HH, 0,
            u1, HH, nullptr, 0, uw2, DD, ub2, nullptr, nullptr, u, DD, 0);

        // x = LN(x + u*mi)*mi
        ln_kernel<<<ROWS/8, 256>>>(u, mask, lg, lb, x);
    }

    // z = relu(x @ out_w1 + out_b1)  -> reuse u1
    gemm_tc<<<dim3(HH/64, ROWS/64), 128>>>(ROWS, HH, DD, 0,
        x, DD, nullptr, 0, out_w1, HH, out_b1, nullptr, nullptr, u1, HH, GRELU);

    // out = (z @ out_w2 + out_b2) * mask
    gemm_tc<<<dim3(DD/64, ROWS/64), 128>>>(ROWS, DD, HH, 0,
        u1, HH, nullptr, 0, out_w2, DD, out_b2, nullptr, mask, out, DD, GMASK);
}

// round 8
// speedup vs baseline: 1.4714x; 1.4714x over previous
#include <cuda_runtime.h>
#include <cstddef>

#define BATCH 16
#define NN 128
#define DD 128
#define EE 64
#define HH 256
#define ROWS (BATCH*NN)   // 2048
#define EPSLN 1e-5f

// ---------------- scratch (static device buffers, no allocation) ----------------
__device__ float g_x[ROWS*DD];
__device__ float g_np[ROWS*HH];
__device__ float g_s[ROWS*HH];
__device__ float g_cnt[ROWS];

// ---------------- helpers ----------------
__device__ __forceinline__ unsigned f2tf(float f) {
    unsigned r;
    asm("cvt.rna.tf32.f32 %0, %1;" : "=r"(r) : "f"(f));
    return r;
}

// hi/lo split: hi = tf32(v), lo = tf32(v - hi)   (3xTF32 scheme)
__device__ __forceinline__ void tfsplit(float v, unsigned& hi, unsigned& lo) {
    hi = f2tf(v);
    lo = f2tf(v - __uint_as_float(hi));
}

__device__ __forceinline__ void mma_tf32(float* d,
                                         unsigned a0, unsigned a1, unsigned a2, unsigned a3,
                                         unsigned b0, unsigned b1) {
    asm volatile("mma.sync.aligned.m16n8k8.row.col.f32.tf32.tf32.f32 "
                 "{%0,%1,%2,%3}, {%4,%5,%6,%7}, {%8,%9}, {%0,%1,%2,%3};"
                 : "+f"(d[0]), "+f"(d[1]), "+f"(d[2]), "+f"(d[3])
                 : "r"(a0), "r"(a1), "r"(a2), "r"(a3), "r"(b0), "r"(b1));
}

// 16-row warp-tile GEMM: acc[NT][4] += A(16 x 8*KSTEPS) @ W(8*KSTEPS x N)
// A in smem (fp32), split into two segments at k-step K1S (segment strides
// must be ≡ 4 mod 32 for conflict-free frag LDS). W streamed from gmem.
// 3xTF32: AhBh + AlBh + AhBl. Warp covers cols [colBase, colBase+NT*8).
template<int KSTEPS, int K1S, int NT>
__device__ __forceinline__ void tile_gemm16(
    const float* sA0, int lda0,
    const float* sA1, int lda1,
    const float* __restrict__ Wg, int ldw, int colBase,
    int r, int c, float acc[NT][4]) {
#pragma unroll 4
    for (int ks = 0; ks < KSTEPS; ks++) {
        const float* sA = (ks < K1S) ? sA0 : sA1;
        int lda = (ks < K1S) ? lda0 : lda1;
        int kofs = (ks < K1S) ? ks*8 : (ks - K1S)*8;
        unsigned ah0, al0, ah1, al1, ah2, al2, ah3, al3;
        tfsplit(sA[r*lda + kofs + c],           ah0, al0);
        tfsplit(sA[(r + 8)*lda + kofs + c],     ah1, al1);
        tfsplit(sA[r*lda + kofs + c + 4],       ah2, al2);
        tfsplit(sA[(r + 8)*lda + kofs + c + 4], ah3, al3);
        int krow = ks*8;
#pragma unroll
        for (int nt = 0; nt < NT; nt++) {
            int col = colBase + nt*8 + r;
            unsigned bh0, bl0, bh1, bl1;
            tfsplit(Wg[(krow + c)*ldw + col],     bh0, bl0);
            tfsplit(Wg[(krow + c + 4)*ldw + col], bh1, bl1);
            mma_tf32(acc[nt], ah0, ah1, ah2, ah3, bh0, bh1);
            mma_tf32(acc[nt], al0, al1, al2, al3, bh0, bh1);
            mma_tf32(acc[nt], ah0, ah1, ah2, ah3, bl0, bl1);
        }
    }
}

// ---------------- prep: x = nodes * mask ----------------
__global__ void prep_x_kernel(const float* __restrict__ nodes,
                              const int* __restrict__ mask,
                              float* __restrict__ x) {
    int row = blockIdx.x;
    int d = threadIdx.x;
    float mi = mask[row] ? 1.f : 0.f;
    x[row*DD + d] = nodes[row*DD + d] * mi;
}

// cnt[b*N+i] = mask[b,i] * sum_j mask[b,j]
__global__ void prep_cnt_kernel(const int* __restrict__ mask,
                                float* __restrict__ cnt) {
    int b = blockIdx.x;
    int j = threadIdx.x;
    __shared__ float red[NN];
    float m = mask[b*NN + j] ? 1.f : 0.f;
    red[j] = m;
    __syncthreads();
    for (int s2 = 64; s2 > 0; s2 >>= 1) {
        if (j < s2) red[j] += red[j + s2];
        __syncthreads();
    }
    cnt[b*NN + j] = m * red[0];
}

// ---------------- np head: np = x @ w1n  (layer 0 only) ----------------
__global__ __launch_bounds__(256) void np_head(
    const float* __restrict__ x,
    const float* __restrict__ w1n,     // (128,256)
    float* __restrict__ np_out) {
    __shared__ __align__(16) float sX[16*132];
    int R0 = blockIdx.x * 16;
    int t = threadIdx.x, w = t >> 5, lane = t & 31;
    int r = lane >> 2, c = lane & 3;

    const float4* sx = (const float4*)(x + (size_t)R0*DD);
#pragma unroll
    for (int g = t; g < 16*32; g += 256) {
        float4 v = sx[g];
        int row = g >> 5, c4 = (g & 31)*4;
        *(float4*)&sX[row*132 + c4] = v;
    }
    __syncthreads();

    float acc[4][4];
#pragma unroll
    for (int nt = 0; nt < 4; nt++)
#pragma unroll
        for (int i = 0; i < 4; i++) acc[nt][i] = 0.f;
    tile_gemm16<16,16,4>(sX, 132, sX, 132, w1n, HH, w*32, r, c, acc);

#pragma unroll
    for (int nt = 0; nt < 4; nt++)
#pragma unroll
        for (int i2 = 0; i2 < 2; i2++)
#pragma unroll
            for (int j = 0; j < 2; j++) {
                int row = R0 + r + i2*8;
                int col = w*32 + nt*8 + 2*c + j;
                np_out[(size_t)row*HH + col] = acc[nt][i2*2 + j];
            }
}

// ---------------- tf32 tensor-core edge kernel (R6 layout, verified) ----------
// s[b,i,h] = m_i * sum_j m_j * relu( np[b,i,h] + b1[h] + sum_e E[j,e]*W[e,h] )
__global__ __launch_bounds__(256, 2)
void edge_msg_tc(const float* __restrict__ edges,
                 const float* __restrict__ We,    // (64,256)
                 const float* __restrict__ b1,    // (256)
                 const float* __restrict__ np,    // (ROWS,256)
                 const int* __restrict__ mask,
                 float* __restrict__ s_out) {
    __shared__ __align__(16) unsigned sE[128 * 68];  // tf32 bits
    __shared__ float smj[NN];

    int row = blockIdx.x;
    int b = row >> 7;
    int t = threadIdx.x;
    int w = t >> 5;
    int lane = t & 31;
    int hb = w * 32;
    int r = lane >> 2;
    int c = lane & 3;

    const float4* src = (const float4*)(edges + (size_t)row * NN * EE);
#pragma unroll
    for (int g = t; g < 2048; g += 256) {
        float4 v = src[g];
        int rr = g >> 4, c4 = (g & 15) * 4;
        unsigned* d = &sE[rr * 68 + c4];
        d[0] = f2tf(v.x); d[1] = f2tf(v.y); d[2] = f2tf(v.z); d[3] = f2tf(v.w);
    }
    if (t < NN) smj[t] = mask[b*NN + t] ? 1.f : 0.f;

    unsigned B0[4][8], B1[4][8];
#pragma unroll
    for (int nt = 0; nt < 4; nt++) {
        int col = hb + nt*8 + r;
#pragma unroll
        for (int k = 0; k < 8; k++) {
            B0[nt][k] = f2tf(We[(k*8 + c)     * HH + col]);
            B1[nt][k] = f2tf(We[(k*8 + c + 4) * HH + col]);
        }
    }

    float npv0[4], npv1[4];
#pragma unroll
    for (int nt = 0; nt < 4; nt++) {
        int h = hb + nt*8 + 2*c;
        npv0[nt] = np[(size_t)row*HH + h]     + b1[h];
        npv1[nt] = np[(size_t)row*HH + h + 1] + b1[h + 1];
    }

    float s0[4] = {0.f, 0.f, 0.f, 0.f};
    float s1[4] = {0.f, 0.f, 0.f, 0.f};

    __syncthreads();

#pragma unroll 1
    for (int m0 = 0; m0 < 8; m0++) {
        float acc[4][4];
#pragma unroll
        for (int nt = 0; nt < 4; nt++) {
            acc[nt][0] = 0.f; acc[nt][1] = 0.f; acc[nt][2] = 0.f; acc[nt][3] = 0.f;
        }
        int rbase0 = (m0*16 + r) * 68;
        int rbase1 = (m0*16 + r + 8) * 68;
#pragma unroll
        for (int k = 0; k < 8; k++) {
            unsigned a0 = sE[rbase0 + k*8 + c];
            unsigned a1 = sE[rbase1 + k*8 + c];
            unsigned a2 = sE[rbase0 + k*8 + c + 4];
            unsigned a3 = sE[rbase1 + k*8 + c + 4];
#pragma unroll
            for (int nt = 0; nt < 4; nt++)
                mma_tf32(acc[nt], a0, a1, a2, a3, B0[nt][k], B1[nt][k]);
        }
        float mj0 = smj[m0*16 + r];
        float mj1 = smj[m0*16 + r + 8];
#pragma unroll
        for (int nt = 0; nt < 4; nt++) {
            s0[nt] += mj0 * fmaxf(acc[nt][0] + npv0[nt], 0.f)
                    + mj1 * fmaxf(acc[nt][2] + npv0[nt], 0.f);
            s1[nt] += mj0 * fmaxf(acc[nt][1] + npv1[nt], 0.f)
                    + mj1 * fmaxf(acc[nt][3] + npv1[nt], 0.f);
        }
    }

#pragma unroll
    for (int off = 4; off < 32; off <<= 1) {
#pragma unroll
        for (int nt = 0; nt < 4; nt++) {
            s0[nt] += __shfl_xor_sync(0xffffffffu, s0[nt], off);
            s1[nt] += __shfl_xor_sync(0xffffffffu, s1[nt], off);
        }
    }

    float mi = mask[row] ? 1.f : 0.f;
    if (lane < 4) {
#pragma unroll
        for (int nt = 0; nt < 4; nt++) {
            int h = hb + nt*8 + 2*lane;
            s_out[(size_t)row*HH + h]     = mi * s0[nt];
            s_out[(size_t)row*HH + h + 1] = mi * s1[nt];
        }
    }
}

// ---------------- fused layer tail ----------------
// Per 16-row block: agg = s@w2 + cnt*b2; u1 = relu([x|agg]@uw1 + ub1);
// u = u1@uw2 + ub2; x = LN(x + u*mi)*mi; np_next = x@w1n_next (optional).
__global__ __launch_bounds__(256) void layer_tail(
    const float* __restrict__ s,
    float* __restrict__ x,
    const float* __restrict__ cnt,
    const int* __restrict__ mask,
    const float* __restrict__ w2,  const float* __restrict__ b2,
    const float* __restrict__ uw1, const float* __restrict__ ub1,
    const float* __restrict__ uw2, const float* __restrict__ ub2,
    const float* __restrict__ lng, const float* __restrict__ lnb,
    const float* __restrict__ w1n_next, float* __restrict__ np_out) {
    // Region reuse: RA = sS -> sU1 -> sXnew ; RB = x rows ; RC = sAgg -> sU
    __shared__ __align__(16) float RA[16*260];
    __shared__ __align__(16) float RB[16*132];
    __shared__ __align__(16) float RC[16*260];
    __shared__ float sCnt[16];
    __shared__ float sMi[16];

    int R0 = blockIdx.x * 16;
    int t = threadIdx.x, w = t >> 5, lane = t & 31;
    int r = lane >> 2, c = lane & 3;

    // stage s rows (16x256) and x rows (16x128)
    {
        const float4* ss = (const float4*)(s + (size_t)R0*HH);
#pragma unroll
        for (int g = t; g < 16*64; g += 256) {
            float4 v = ss[g];
            int row = g >> 6, c4 = (g & 63)*4;
            *(float4*)&RA[row*260 + c4] = v;
        }
        const float4* sx = (const float4*)(x + (size_t)R0*DD);
#pragma unroll
        for (int g = t; g < 16*32; g += 256) {
            float4 v = sx[g];
            int row = g >> 5, c4 = (g & 31)*4;
            *(float4*)&RB[row*132 + c4] = v;
        }
        if (t < 16) { sCnt[t] = cnt[R0 + t]; sMi[t] = mask[R0 + t] ? 1.f : 0.f; }
    }
    __syncthreads();

    // G1: agg = s@w2 + cnt*b2 -> RC
    {
        float acc[4][4];
#pragma unroll
        for (int nt = 0; nt < 4; nt++)
#pragma unroll
            for (int i = 0; i < 4; i++) acc[nt][i] = 0.f;
        tile_gemm16<32,32,4>(RA, 260, RA, 260, w2, HH, w*32, r, c, acc);
#pragma unroll
        for (int nt = 0; nt < 4; nt++)
#pragma unroll
            for (int i2 = 0; i2 < 2; i2++)
#pragma unroll
                for (int j = 0; j < 2; j++) {
                    int row = r + i2*8;
                    int col = w*32 + nt*8 + 2*c + j;
                    RC[row*260 + col] = acc[nt][i2*2 + j] + sCnt[row]*b2[col];
                }
    }
    __syncthreads();

    // G2: u1 = relu([x|agg]@uw1 + ub1) -> RA
    {
        float acc[4][4];
#pragma unroll
        for (int nt = 0; nt < 4; nt++)
#pragma unroll
            for (int i = 0; i < 4; i++) acc[nt][i] = 0.f;
        tile_gemm16<48,16,4>(RB, 132, RC, 260, uw1, HH, w*32, r, c, acc);
        __syncthreads();   // RA(s) fully consumed by G1 already; safe, but keep order vs G1 readers
#pragma unroll
        for (int nt = 0; nt < 4; nt++)
#pragma unroll
            for (int i2 = 0; i2 < 2; i2++)
#pragma unroll
                for (int j = 0; j < 2; j++) {
                    int row = r + i2*8;
                    int col = w*32 + nt*8 + 2*c + j;
                    RA[row*260 + col] = fmaxf(acc[nt][i2*2 + j] + ub1[col], 0.f);
                }
    }
    __syncthreads();

    // G3: u = u1@uw2 + ub2 -> RC (stride 132), 8 warps x 16 cols
    {
        float acc[2][4];
#pragma unroll
        for (int nt = 0; nt < 2; nt++)
#pragma unroll
            for (int i = 0; i < 4; i++) acc[nt][i] = 0.f;
        tile_gemm16<32,32,2>(RA, 260, RA, 260, uw2, DD, w*16, r, c, acc);
        __syncthreads();   // RC(agg) consumed by G2
#pragma unroll
        for (int nt = 0; nt < 2; nt++)
#pragma unroll
            for (int i2 = 0; i2 < 2; i2++)
#pragma unroll
                for (int j = 0; j < 2; j++) {
                    int row = r + i2*8;
                    int col = w*16 + nt*8 + 2*c + j;
                    RC[row*132 + col] = acc[nt][i2*2 + j] + ub2[col];
                }
    }
    __syncthreads();

    // LN: rows 2w, 2w+1. x_new = LN(x_old + u*mi)*g+b, then *mi -> gmem + RA
    {
#pragma unroll
        for (int rr = 2*w; rr <= 2*w + 1; rr++) {
            float mi = sMi[rr];
            float v[4];
#pragma unroll
            for (int q = 0; q < 4; q++) {
                int col = lane + q*32;
                v[q] = RB[rr*132 + col] + RC[rr*132 + col] * mi;
            }
            float sum = v[0] + v[1] + v[2] + v[3];
#pragma unroll
            for (int o = 16; o > 0; o >>= 1) sum += __shfl_xor_sync(0xffffffffu, sum, o);
            float mu = sum * (1.f / DD);
            float var = 0.f;
#pragma unroll
            for (int q = 0; q < 4; q++) { float d2 = v[q] - mu; var += d2*d2; }
#pragma unroll
            for (int o = 16; o > 0; o >>= 1) var += __shfl_xor_sync(0xffffffffu, var, o);
            float rstd = rsqrtf(var * (1.f / DD) + EPSLN);
#pragma unroll
            for (int q = 0; q < 4; q++) {
                int col = lane + q*32;
                float xn = ((v[q] - mu) * rstd * lng[col] + lnb[col]) * mi;
                x[(size_t)(R0 + rr)*DD + col] = xn;
                RA[rr*132 + col] = xn;
            }
        }
    }

    // np for next layer: np = x_new @ w1n_next
    if (w1n_next != nullptr) {
        __syncthreads();
        float acc[4][4];
#pragma unroll
        for (int nt = 0; nt < 4; nt++)
#pragma unroll
            for (int i = 0; i < 4; i++) acc[nt][i] = 0.f;
        tile_gemm16<16,16,4>(RA, 132, RA, 132, w1n_next, HH, w*32, r, c, acc);
#pragma unroll
        for (int nt = 0; nt < 4; nt++)
#pragma unroll
            for (int i2 = 0; i2 < 2; i2++)
#pragma unroll
                for (int j = 0; j < 2; j++) {
                    int row = R0 + r + i2*8;
                    int col = w*32 + nt*8 + 2*c + j;
                    np_out[(size_t)row*HH + col] = acc[nt][i2*2 + j];
                }
    }
}

// ---------------- fused output MLP ----------------
// out = (relu(x@ow1 + ob1) @ ow2 + ob2) * mask
__global__ __launch_bounds__(256) void final_mlp(
    const float* __restrict__ x,
    const int* __restrict__ mask,
    const float* __restrict__ ow1, const float* __restrict__ ob1,
    const float* __restrict__ ow2, const float* __restrict__ ob2,
    float* __restrict__ out) {
    __shared__ __align__(16) float sX[16*132];
    __shared__ __align__(16) float sZ[16*260];
    __shared__ float sMi[16];

    int R0 = blockIdx.x * 16;
    int t = threadIdx.x, w = t >> 5, lane = t & 31;
    int r = lane >> 2, c = lane & 3;

    const float4* sx = (const float4*)(x + (size_t)R0*DD);
#pragma unroll
    for (int g = t; g < 16*32; g += 256) {
        float4 v = sx[g];
        int row = g >> 5, c4 = (g & 31)*4;
        *(float4*)&sX[row*132 + c4] = v;
    }
    if (t < 16) sMi[t] = mask[R0 + t] ? 1.f : 0.f;
    __syncthreads();

    // z = relu(x@ow1 + ob1) -> sZ
    {
        float acc[4][4];
#pragma unroll
        for (int nt = 0; nt < 4; nt++)
#pragma unroll
            for (int i = 0; i < 4; i++) acc[nt][i] = 0.f;
        tile_gemm16<16,16,4>(sX, 132, sX, 132, ow1, HH, w*32, r, c, acc);
#pragma unroll
        for (int nt = 0; nt < 4; nt++)
#pragma unroll
            for (int i2 = 0; i2 < 2; i2++)
#pragma unroll
                for (int j = 0; j < 2; j++) {
                    int row = r + i2*8;
                    int col = w*32 + nt*8 + 2*c + j;
                    sZ[row*260 + col] = fmaxf(acc[nt][i2*2 + j] + ob1[col], 0.f);
                }
    }
    __syncthreads();

    // out = (z@ow2 + ob2)*mi
    {
        float acc[2][4];
#pragma unroll
        for (int nt = 0; nt < 2; nt++)
#pragma unroll
            for (int i = 0; i < 4; i++) acc[nt][i] = 0.f;
        tile_gemm16<32,32,2>(sZ, 260, sZ, 260, ow2, DD, w*16, r, c, acc);
#pragma unroll
        for (int nt = 0; nt < 2; nt++)
#pragma unroll
            for (int i2 = 0; i2 < 2; i2++)
#pragma unroll
                for (int j = 0; j < 2; j++) {
                    int row = r + i2*8;
                    int col = w*16 + nt*8 + 2*c + j;
                    out[(size_t)(R0 + row)*DD + col] =
                        (acc[nt][i2*2 + j] + ob2[col]) * sMi[row];
                }
    }
}

// ---------------- host launch ----------------
extern "C" void kernel_launch(void* const* d_in, const int* in_sizes, int n_in,
                              void* d_out, int out_size) {
    const float* nodes  = (const float*)d_in[0];
    const float* edges  = (const float*)d_in[1];
    const int*   mask   = (const int*)d_in[2];
    const float* msg_w1 = (const float*)d_in[3];   // (L,192,256)
    const float* msg_b1 = (const float*)d_in[4];   // (L,256)
    const float* msg_w2 = (const float*)d_in[5];   // (L,256,256)
    const float* msg_b2 = (const float*)d_in[6];   // (L,256)
    const float* upd_w1 = (const float*)d_in[7];   // (L,384,256)
    const float* upd_b1 = (const float*)d_in[8];   // (L,256)
    const float* upd_w2 = (const float*)d_in[9];   // (L,256,128)
    const float* upd_b2 = (const float*)d_in[10];  // (L,128)
    const float* ln_g   = (const float*)d_in[11];  // (L,128)
    const float* ln_b   = (const float*)d_in[12];  // (L,128)
    const float* out_w1 = (const float*)d_in[13];  // (128,256)
    const float* out_b1 = (const float*)d_in[14];  // (256)
    const float* out_w2 = (const float*)d_in[15];  // (256,128)
    const float* out_b2 = (const float*)d_in[16];  // (128)
    float* out = (float*)d_out;

    float *x, *np, *s, *cnt;
    cudaGetSymbolAddress((void**)&x,   g_x);
    cudaGetSymbolAddress((void**)&np,  g_np);
    cudaGetSymbolAddress((void**)&s,   g_s);
    cudaGetSymbolAddress((void**)&cnt, g_cnt);

    prep_x_kernel<<<ROWS, DD>>>(nodes, mask, x);
    prep_cnt_kernel<<<BATCH, NN>>>(mask, cnt);

    // layer-0 np
    np_head<<<ROWS/16, 256>>>(x, msg_w1, np);

    for (int l = 0; l < 3; l++) {
        const float* w1n = msg_w1 + (size_t)l * 192 * HH;
        const float* w1e = w1n + (size_t)DD * HH;
        const float* b1  = msg_b1 + (size_t)l * HH;
        const float* w2  = msg_w2 + (size_t)l * HH * HH;
        const float* b2  = msg_b2 + (size_t)l * HH;
        const float* uw1 = upd_w1 + (size_t)l * 384 * HH;
        const float* ub1 = upd_b1 + (size_t)l * HH;
        const float* uw2 = upd_w2 + (size_t)l * HH * DD;
        const float* ub2 = upd_b2 + (size_t)l * DD;
        const float* lg  = ln_g + (size_t)l * DD;
        const float* lb  = ln_b + (size_t)l * DD;
        const float* w1n_next = (l < 2) ? (msg_w1 + (size_t)(l+1) * 192 * HH) : nullptr;

        edge_msg_tc<<<ROWS, 256>>>(edges, w1e, b1, np, mask, s);

        layer_tail<<<ROWS/16, 256>>>(s, x, cnt, mask,
                                     w2, b2, uw1, ub1, uw2, ub2, lg, lb,
                                     w1n_next, np);
    }

    final_mlp<<<ROWS/16, 256>>>(x, mask, out_w1, out_b1, out_w2, out_b2, out);
}

// round 9
// speedup vs baseline: 1.5606x; 1.0606x over previous
#include <cuda_runtime.h>
#include <cstddef>

#define BATCH 16
#define NN 128
#define DD 128
#define EE 64
#define HH 256
#define ROWS (BATCH*NN)   // 2048
#define EPSLN 1e-5f

#define GRELU 1
#define GMASK 2

// ---------------- scratch (static device buffers, no allocation) ----------------
__device__ float g_x[ROWS*DD];
__device__ float g_np[ROWS*HH];
__device__ float g_s[ROWS*HH];
__device__ float g_agg[ROWS*HH];
__device__ float g_u1[ROWS*HH];
__device__ float g_u[ROWS*DD];
__device__ float g_cnt[ROWS];

// ---------------- helpers ----------------
__device__ __forceinline__ unsigned f2tf(float f) {
    unsigned r;
    asm("cvt.rna.tf32.f32 %0, %1;" : "=r"(r) : "f"(f));
    return r;
}

// hi/lo split: hi = tf32(v), lo = tf32(v - hi)   (3xTF32 scheme)
__device__ __forceinline__ void tfsplit(float v, unsigned& hi, unsigned& lo) {
    hi = f2tf(v);
    lo = f2tf(v - __uint_as_float(hi));
}

__device__ __forceinline__ void mma_tf32(float* d,
                                         unsigned a0, unsigned a1, unsigned a2, unsigned a3,
                                         unsigned b0, unsigned b1) {
    asm volatile("mma.sync.aligned.m16n8k8.row.col.f32.tf32.tf32.f32 "
                 "{%0,%1,%2,%3}, {%4,%5,%6,%7}, {%8,%9}, {%0,%1,%2,%3};"
                 : "+f"(d[0]), "+f"(d[1]), "+f"(d[2]), "+f"(d[3])
                 : "r"(a0), "r"(a1), "r"(a2), "r"(a3), "r"(b0), "r"(b1));
}

// ---------------- prep: x = nodes * mask ----------------
__global__ void prep_x_kernel(const float* __restrict__ nodes,
                              const int* __restrict__ mask,
                              float* __restrict__ x) {
    int row = blockIdx.x;
    int d = threadIdx.x;
    float mi = mask[row] ? 1.f : 0.f;
    x[row*DD + d] = nodes[row*DD + d] * mi;
}

// cnt[b*N+i] = mask[b,i] * sum_j mask[b,j]
__global__ void prep_cnt_kernel(const int* __restrict__ mask,
                                float* __restrict__ cnt) {
    int b = blockIdx.x;
    int j = threadIdx.x;
    __shared__ float red[NN];
    float m = mask[b*NN + j] ? 1.f : 0.f;
    red[j] = m;
    __syncthreads();
    for (int s2 = 64; s2 > 0; s2 >>= 1) {
        if (j < s2) red[j] += red[j + s2];
        __syncthreads();
    }
    cnt[b*NN + j] = m * red[0];
}

// ---------------- tf32 tensor-core edge kernel, cp.async pipelined ------------
// s[b,i,h] = m_i * sum_j m_j * relu( np[b,i,h] + b1[h] + sum_e E[j,e]*W[e,h] )
// 8 pipeline stages of 16 j-rows (4KB each) over the 128x68-word smem tile;
// stage m0+3 is in flight while m-tile m0 computes. A operands are raw fp32
// bits (HMMA tf32 truncates); B (weights) converted RNA.
__global__ __launch_bounds__(256, 2)
void edge_msg_tc(const float* __restrict__ edges,
                 const float* __restrict__ We,    // (64,256)
                 const float* __restrict__ b1,    // (256)
                 const float* __restrict__ np,    // (ROWS,256)
                 const int* __restrict__ mask,
                 float* __restrict__ s_out) {
    __shared__ __align__(16) float sE[128 * 68];  // fp32 bits, stride 68
    __shared__ float smj[NN];

    int row = blockIdx.x;
    int b = row >> 7;
    int t = threadIdx.x;
    int w = t >> 5;
    int lane = t & 31;
    int hb = w * 32;
    int r = lane >> 2;
    int c = lane & 3;

    const char* src = (const char*)(edges + (size_t)row * NN * EE);
    unsigned sbase = (unsigned)__cvta_generic_to_shared(sE);
    int srr = t >> 4;               // row within stage (0..15)
    int sc4 = (t & 15) * 4;         // word col (0..60)

#define ISSUE_STAGE(s_) do {                                                  \
    unsigned dst = sbase + (unsigned)((((s_)*16 + srr)*68 + sc4)*4);          \
    const char* gsrc = src + ((size_t)((s_)*256 + t))*16;                     \
    asm volatile("cp.async.cg.shared.global [%0], [%1], 16;\n"                \
                 "cp.async.commit_group;" :: "r"(dst), "l"(gsrc));            \
} while (0)

    ISSUE_STAGE(0); ISSUE_STAGE(1); ISSUE_STAGE(2);

    if (t < NN) smj[t] = mask[b*NN + t] ? 1.f : 0.f;

    // B fragments (RNA tf32)
    unsigned B0[4][8], B1[4][8];
#pragma unroll
    for (int nt = 0; nt < 4; nt++) {
        int col = hb + nt*8 + r;
#pragma unroll
        for (int k = 0; k < 8; k++) {
            B0[nt][k] = f2tf(We[(k*8 + c)     * HH + col]);
            B1[nt][k] = f2tf(We[(k*8 + c + 4) * HH + col]);
        }
    }

    float npv0[4], npv1[4];
#pragma unroll
    for (int nt = 0; nt < 4; nt++) {
        int h = hb + nt*8 + 2*c;
        npv0[nt] = np[(size_t)row*HH + h]     + b1[h];
        npv1[nt] = np[(size_t)row*HH + h + 1] + b1[h + 1];
    }

    float s0[4] = {0.f, 0.f, 0.f, 0.f};
    float s1[4] = {0.f, 0.f, 0.f, 0.f};

#pragma unroll
    for (int m0 = 0; m0 < 8; m0++) {
        if (m0 + 3 < 8) ISSUE_STAGE(m0 + 3);
        if (m0 <= 4)      asm volatile("cp.async.wait_group 3;");
        else if (m0 == 5) asm volatile("cp.async.wait_group 2;");
        else if (m0 == 6) asm volatile("cp.async.wait_group 1;");
        else              asm volatile("cp.async.wait_group 0;");
        __syncthreads();

        float acc[4][4];
#pragma unroll
        for (int nt = 0; nt < 4; nt++) {
            acc[nt][0] = 0.f; acc[nt][1] = 0.f; acc[nt][2] = 0.f; acc[nt][3] = 0.f;
        }
        int rbase0 = (m0*16 + r) * 68;
        int rbase1 = (m0*16 + r + 8) * 68;
#pragma unroll
        for (int k = 0; k < 8; k++) {
            unsigned a0 = __float_as_uint(sE[rbase0 + k*8 + c]);
            unsigned a1 = __float_as_uint(sE[rbase1 + k*8 + c]);
            unsigned a2 = __float_as_uint(sE[rbase0 + k*8 + c + 4]);
            unsigned a3 = __float_as_uint(sE[rbase1 + k*8 + c + 4]);
#pragma unroll
            for (int nt = 0; nt < 4; nt++)
                mma_tf32(acc[nt], a0, a1, a2, a3, B0[nt][k], B1[nt][k]);
        }
        float mj0 = smj[m0*16 + r];
        float mj1 = smj[m0*16 + r + 8];
#pragma unroll
        for (int nt = 0; nt < 4; nt++) {
            s0[nt] += mj0 * fmaxf(acc[nt][0] + npv0[nt], 0.f)
                    + mj1 * fmaxf(acc[nt][2] + npv0[nt], 0.f);
            s1[nt] += mj0 * fmaxf(acc[nt][1] + npv1[nt], 0.f)
                    + mj1 * fmaxf(acc[nt][3] + npv1[nt], 0.f);
        }
    }
#undef ISSUE_STAGE

#pragma unroll
    for (int off = 4; off < 32; off <<= 1) {
#pragma unroll
        for (int nt = 0; nt < 4; nt++) {
            s0[nt] += __shfl_xor_sync(0xffffffffu, s0[nt], off);
            s1[nt] += __shfl_xor_sync(0xffffffffu, s1[nt], off);
        }
    }

    float mi = mask[row] ? 1.f : 0.f;
    if (lane < 4) {
#pragma unroll
        for (int nt = 0; nt < 4; nt++) {
            int h = hb + nt*8 + 2*lane;
            s_out[(size_t)row*HH + h]     = mi * s0[nt];
            s_out[(size_t)row*HH + h + 1] = mi * s1[nt];
        }
    }
}

// ---------------- 3xTF32 split tensor-core GEMM, double-buffered ----------------
// C(M,N) = epilogue( [A | A2](M,K) @ W(K,N) ), near-fp32 accuracy via
// Ah*Bh + Al*Bh + Ah*Bl. Block tile 64x64, 128 threads (2x2 warps, warp 32x32),
// K-chunk 32. Requires M%64==0, N%64==0, K%32==0, K1%32==0.
__global__ __launch_bounds__(128)
void gemm_tc(int M, int N, int K, int K1,
             const float* __restrict__ A, int lda,
             const float* __restrict__ A2, int lda2,
             const float* __restrict__ W, int ldw,
             const float* __restrict__ bias,
             const float* __restrict__ rowscale,
             const int* __restrict__ maskrow,
             float* __restrict__ C, int ldc, int flags) {
    __shared__ __align__(16) float sA[2][64 * 36];
    __shared__ __align__(16) float sB[2][32 * 72];

    int tid = threadIdx.x;
    int w = tid >> 5;
    int lane = tid & 31;
    int wm = w & 1, wn = w >> 1;
    int r = lane >> 2, c = lane & 3;

    int bm = blockIdx.y * 64, bn = blockIdx.x * 64;

    float acc[2][4][4];
#pragma unroll
    for (int mt = 0; mt < 2; mt++)
#pragma unroll
        for (int nt = 0; nt < 4; nt++)
#pragma unroll
            for (int i = 0; i < 4; i++) acc[mt][nt][i] = 0.f;

    float4 pa[4], pb[4];

#define PREFETCH(k0_) do {                                                   \
    _Pragma("unroll")                                                        \
    for (int q = 0; q < 4; q++) {                                            \
        int g = tid + q*128;                                                 \
        int row_ = g >> 3, col4 = (g & 7) * 4;                               \
        int gm = bm + row_, gk = (k0_) + col4;                               \
        if (A2 != nullptr && gk >= K1)                                       \
            pa[q] = *(const float4*)(A2 + (size_t)gm*lda2 + (gk - K1));      \
        else                                                                 \
            pa[q] = *(const float4*)(A + (size_t)gm*lda + gk);               \
    }                                                                        \
    _Pragma("unroll")                                                        \
    for (int q = 0; q < 4; q++) {                                            \
        int g = tid + q*128;                                                 \
        int row_ = g >> 4, col4 = (g & 15) * 4;                              \
        pb[q] = *(const float4*)(W + (size_t)((k0_) + row_)*ldw + bn + col4);\
    }                                                                        \
} while (0)

#define STORE_STAGE(s_) do {                                                 \
    _Pragma("unroll")                                                        \
    for (int q = 0; q < 4; q++) {                                            \
        int g = tid + q*128;                                                 \
        int row_ = g >> 3, col4 = (g & 7) * 4;                               \
        *(float4*)&sA[s_][row_*36 + col4] = pa[q];                           \
    }                                                                        \
    _Pragma("unroll")                                                        \
    for (int q = 0; q < 4; q++) {                                            \
        int g = tid + q*128;                                                 \
        int row_ = g >> 4, col4 = (g & 15) * 4;                              \
        *(float4*)&sB[s_][row_*72 + col4] = pb[q];                           \
    }                                                                        \
} while (0)

    PREFETCH(0);
    STORE_STAGE(0);
    __syncthreads();

    int s = 0;
    for (int k0 = 0; ; ) {
        bool haveNext = (k0 + 32 < K);
        if (haveNext) PREFETCH(k0 + 32);

#pragma unroll
        for (int kk = 0; kk < 4; kk++) {
            unsigned bh0[4], bl0[4], bh1[4], bl1[4];
#pragma unroll
            for (int nt = 0; nt < 4; nt++) {
                int col = wn*32 + nt*8 + r;
                tfsplit(sB[s][(kk*8 + c)     * 72 + col], bh0[nt], bl0[nt]);
                tfsplit(sB[s][(kk*8 + c + 4) * 72 + col], bh1[nt], bl1[nt]);
            }
#pragma unroll
            for (int mt = 0; mt < 2; mt++) {
                int row0 = (wm*32 + mt*16 + r) * 36;
                int row1 = (wm*32 + mt*16 + r + 8) * 36;
                unsigned ah0, al0, ah1, al1, ah2, al2, ah3, al3;
                tfsplit(sA[s][row0 + kk*8 + c],     ah0, al0);
                tfsplit(sA[s][row1 + kk*8 + c],     ah1, al1);
                tfsplit(sA[s][row0 + kk*8 + c + 4], ah2, al2);
                tfsplit(sA[s][row1 + kk*8 + c + 4], ah3, al3);
#pragma unroll
                for (int nt = 0; nt < 4; nt++) {
                    mma_tf32(acc[mt][nt], ah0, ah1, ah2, ah3, bh0[nt], bh1[nt]);
                    mma_tf32(acc[mt][nt], al0, al1, al2, al3, bh0[nt], bh1[nt]);
                    mma_tf32(acc[mt][nt], ah0, ah1, ah2, ah3, bl0[nt], bl1[nt]);
                }
            }
        }

        k0 += 32;
        if (!haveNext) break;
        STORE_STAGE(s ^ 1);
        __syncthreads();
        s ^= 1;
    }
#undef PREFETCH
#undef STORE_STAGE

#pragma unroll
    for (int mt = 0; mt < 2; mt++) {
#pragma unroll
        for (int i2 = 0; i2 < 2; i2++) {
            int gm = bm + wm*32 + mt*16 + r + i2*8;
            float rs = (rowscale != nullptr) ? rowscale[gm] : 1.f;
            float mf = (flags & GMASK) ? (maskrow[gm] ? 1.f : 0.f) : 1.f;
#pragma unroll
            for (int nt = 0; nt < 4; nt++) {
#pragma unroll
                for (int j = 0; j < 2; j++) {
                    int gn = bn + wn*32 + nt*8 + 2*c + j;
                    float v = acc[mt][nt][i2*2 + j];
                    if (bias != nullptr) v += bias[gn] * rs;
                    if (flags & GRELU) v = fmaxf(v, 0.f);
                    v *= mf;
                    C[(size_t)gm*ldc + gn] = v;
                }
            }
        }
    }
}

// ---------------- fused residual + LayerNorm ----------------
__global__ void ln_kernel(const float* __restrict__ u,
                          const int* __restrict__ mask,
                          const float* __restrict__ gw,
                          const float* __restrict__ bw,
                          float* __restrict__ x) {
    int warp = threadIdx.x >> 5;
    int lane = threadIdx.x & 31;
    int row = blockIdx.x * 8 + warp;
    float mi = mask[row] ? 1.f : 0.f;

    float v[4];
#pragma unroll
    for (int q = 0; q < 4; q++) {
        int d = lane + q*32;
        v[q] = x[(size_t)row*DD + d] + u[(size_t)row*DD + d] * mi;
    }
    float s = v[0] + v[1] + v[2] + v[3];
#pragma unroll
    for (int o = 16; o > 0; o >>= 1) s += __shfl_xor_sync(0xffffffffu, s, o);
    float mu = s * (1.f / DD);
    float var = 0.f;
#pragma unroll
    for (int q = 0; q < 4; q++) { float d2 = v[q] - mu; var += d2*d2; }
#pragma unroll
    for (int o = 16; o > 0; o >>= 1) var += __shfl_xor_sync(0xffffffffu, var, o);
    float rstd = rsqrtf(var * (1.f / DD) + EPSLN);
#pragma unroll
    for (int q = 0; q < 4; q++) {
        int d = lane + q*32;
        x[(size_t)row*DD + d] = ((v[q] - mu) * rstd * gw[d] + bw[d]) * mi;
    }
}

// ---------------- host launch ----------------
extern "C" void kernel_launch(void* const* d_in, const int* in_sizes, int n_in,
                              void* d_out, int out_size) {
    const float* nodes  = (const float*)d_in[0];
    const float* edges  = (const float*)d_in[1];
    const int*   mask   = (const int*)d_in[2];
    const float* msg_w1 = (const float*)d_in[3];
    const float* msg_b1 = (const float*)d_in[4];
    const float* msg_w2 = (const float*)d_in[5];
    const float* msg_b2 = (const float*)d_in[6];
    const float* upd_w1 = (const float*)d_in[7];
    const float* upd_b1 = (const float*)d_in[8];
    const float* upd_w2 = (const float*)d_in[9];
    const float* upd_b2 = (const float*)d_in[10];
    const float* ln_g   = (const float*)d_in[11];
    const float* ln_b   = (const float*)d_in[12];
    const float* out_w1 = (const float*)d_in[13];
    const float* out_b1 = (const float*)d_in[14];
    const float* out_w2 = (const float*)d_in[15];
    const float* out_b2 = (const float*)d_in[16];
    float* out = (float*)d_out;

    float *x, *np, *s, *agg, *u1, *u, *cnt;
    cudaGetSymbolAddress((void**)&x,   g_x);
    cudaGetSymbolAddress((void**)&np,  g_np);
    cudaGetSymbolAddress((void**)&s,   g_s);
    cudaGetSymbolAddress((void**)&agg, g_agg);
    cudaGetSymbolAddress((void**)&u1,  g_u1);
    cudaGetSymbolAddress((void**)&u,   g_u);
    cudaGetSymbolAddress((void**)&cnt, g_cnt);

    prep_x_kernel<<<ROWS, DD>>>(nodes, mask, x);
    prep_cnt_kernel<<<BATCH, NN>>>(mask, cnt);

    for (int l = 0; l < 3; l++) {
        const float* w1n = msg_w1 + (size_t)l * 192 * HH;
        const float* w1e = w1n + (size_t)DD * HH;
        const float* b1  = msg_b1 + (size_t)l * HH;
        const float* w2  = msg_w2 + (size_t)l * HH * HH;
        const float* b2  = msg_b2 + (size_t)l * HH;
        const float* uw1 = upd_w1 + (size_t)l * 384 * HH;
        const float* ub1 = upd_b1 + (size_t)l * HH;
        const float* uw2 = upd_w2 + (size_t)l * HH * DD;
        const float* ub2 = upd_b2 + (size_t)l * DD;
        const float* lg  = ln_g + (size_t)l * DD;
        const float* lb  = ln_b + (size_t)l * DD;

        gemm_tc<<<dim3(HH/64, ROWS/64), 128>>>(ROWS, HH, DD, 0,
            x, DD, nullptr, 0, w1n, HH, nullptr, nullptr, nullptr, np, HH, 0);

        edge_msg_tc<<<ROWS, 256>>>(edges, w1e, b1, np, mask, s);

        gemm_tc<<<dim3(HH/64, ROWS/64), 128>>>(ROWS, HH, HH, 0,
            s, HH, nullptr, 0, w2, HH, b2, cnt, nullptr, agg, HH, 0);

        gemm_tc<<<dim3(HH/64, ROWS/64), 128>>>(ROWS, HH, DD + HH, DD,
            x, DD, agg, HH, uw1, HH, ub1, nullptr, nullptr, u1, HH, GRELU);

        gemm_tc<<<dim3(DD/64, ROWS/64), 128>>>(ROWS, DD, HH, 0,
            u1, HH, nullptr, 0, uw2, DD, ub2, nullptr, nullptr, u, DD, 0);

        ln_kernel<<<ROWS/8, 256>>>(u, mask, lg, lb, x);
    }

    gemm_tc<<<dim3(HH/64, ROWS/64), 128>>>(ROWS, HH, DD, 0,
        x, DD, nullptr, 0, out_w1, HH, out_b1, nullptr, nullptr, u1, HH, GRELU);

    gemm_tc<<<dim3(DD/64, ROWS/64), 128>>>(ROWS, DD, HH, 0,
        u1, HH, nullptr, 0, out_w2, DD, out_b2, nullptr, mask, out, DD, GMASK);
}